// round 1
// baseline (speedup 1.0000x reference)
#include <cuda_runtime.h>
#include <math.h>

#define KN      100
#define NTOT    10647
#define NBINS   4096
#define NGRP    128
#define CAP     1024
#define NT      1024
#define IOU_T   0.3f
#define TKWORDS ((NTOT + 31) / 32)

__device__ __forceinline__ float sigm(float x) { return 1.0f / (1.0f + expf(-x)); }

__device__ __forceinline__ unsigned long long make_key(float score, int gi) {
    unsigned int fb = __float_as_uint(score);  // score >= 0 -> bits monotonic
    return ((unsigned long long)fb << 32) |
           (unsigned long long)(0xFFFFFFFFu - (unsigned int)gi);  // lower idx wins ties
}

// conf (sigmoid of objectness channel) for global box index gi of one image
__device__ __forceinline__ float conf_of(int gi, const float* __restrict__ i13,
                                         const float* __restrict__ i26,
                                         const float* __restrict__ i52) {
    const float* img; int S, plane, loc;
    if (gi < 507)       { img = i13; S = 13; plane = 169;  loc = gi; }
    else if (gi < 2535) { img = i26; S = 26; plane = 676;  loc = gi - 507; }
    else                { img = i52; S = 52; plane = 2704; loc = gi - 2535; }
    int a = loc % 3;
    int cell = loc / 3;
    int row = cell / S;
    int col = cell - row * S;
    float v = img[(size_t)(a * 85) * plane + row * S + col];
    return sigm(v);
}

__global__ __launch_bounds__(NT)
void yolo_nms_kernel(const float* __restrict__ o13, const float* __restrict__ o26,
                     const float* __restrict__ o52, const float* __restrict__ anc,
                     const float* __restrict__ thrp, float* __restrict__ out, int B)
{
    __shared__ unsigned int hist[NBINS];
    __shared__ unsigned int gsum[NGRP];
    __shared__ unsigned long long cand[CAP];
    __shared__ unsigned long long wred[32];
    __shared__ int selected[KN];
    __shared__ float boxes[KN][6];
    __shared__ unsigned int nmask[KN][4];
    __shared__ unsigned int keepW[4];
    __shared__ float sAnc[18];
    __shared__ unsigned int taken[TKWORDS];
    __shared__ int sB, sCnt, sOvf;

    const int tid = threadIdx.x;
    const int b = blockIdx.x;
    const float thr = *thrp;

    const float* img13 = o13 + (size_t)b * 255 * 169;
    const float* img26 = o26 + (size_t)b * 255 * 676;
    const float* img52 = o52 + (size_t)b * 255 * 2704;

    for (int i = tid; i < NBINS; i += NT) hist[i] = 0;
    if (tid < 18) sAnc[tid] = anc[tid];
    if (tid == 0) { sCnt = 0; sOvf = 0; }
    __syncthreads();

    // ---- Pass 1: histogram of score bins (only objectness channel read) ----
    for (int gi = tid; gi < NTOT; gi += NT) {
        float conf = conf_of(gi, img13, img26, img52);
        float score = (conf > thr) ? conf : 0.0f;
        atomicAdd(&hist[__float_as_uint(score) >> 18], 1u);
    }
    __syncthreads();

    // ---- two-level suffix scan to find threshold bin b* ----
    if (tid < NGRP) {
        unsigned int s = 0;
        for (int j = 0; j < 32; j++) s += hist[tid * 32 + j];
        gsum[tid] = s;
    }
    __syncthreads();
    if (tid == 0) {
        unsigned int cum = 0;
        int bstar = 0;
        for (int g = NGRP - 1; g >= 0; g--) {
            if (cum + gsum[g] >= KN) {
                for (int bb = g * 32 + 31; bb >= g * 32; bb--) {
                    if (cum + hist[bb] >= KN) { bstar = bb; break; }
                    cum += hist[bb];
                }
                break;
            }
            cum += gsum[g];
        }
        sB = bstar;
    }
    __syncthreads();
    const unsigned int bstar = (unsigned int)sB;

    // ---- Pass 2: collect candidate keys (bin >= b*) ----
    for (int gi = tid; gi < NTOT; gi += NT) {
        float conf = conf_of(gi, img13, img26, img52);
        float score = (conf > thr) ? conf : 0.0f;
        if ((__float_as_uint(score) >> 18) >= bstar) {
            int pos = atomicAdd(&sCnt, 1);
            if (pos < CAP) cand[pos] = make_key(score, gi);
            else sOvf = 1;
        }
    }
    __syncthreads();

    if (!sOvf) {
        const int T = sCnt;           // 100 <= T <= CAP here
        if (tid >= T) cand[tid] = 0ULL;   // NT == CAP, each thread pads one slot
        __syncthreads();
        // bitonic sort, descending
        for (int k = 2; k <= CAP; k <<= 1) {
            for (int j = k >> 1; j > 0; j >>= 1) {
                int ixj = tid ^ j;
                if (ixj > tid) {
                    bool up = ((tid & k) == 0);
                    unsigned long long A = cand[tid], Bv = cand[ixj];
                    bool sw = up ? (A < Bv) : (A > Bv);
                    if (sw) { cand[tid] = Bv; cand[ixj] = A; }
                }
                __syncthreads();
            }
        }
        if (tid < KN)
            selected[tid] = (int)(0xFFFFFFFFu - (unsigned int)(cand[tid] & 0xFFFFFFFFull));
    } else {
        // ---- fallback: exact block-wide selection sort (pathological inputs) ----
        for (int i = tid; i < TKWORDS; i += NT) taken[i] = 0;
        __syncthreads();
        for (int k = 0; k < KN; k++) {
            unsigned long long best = 0;
            for (int gi = tid; gi < NTOT; gi += NT) {
                if ((taken[gi >> 5] >> (gi & 31)) & 1u) continue;
                float conf = conf_of(gi, img13, img26, img52);
                float score = (conf > thr) ? conf : 0.0f;
                unsigned long long key = make_key(score, gi);
                if (key > best) best = key;
            }
            for (int off = 16; off; off >>= 1) {
                unsigned long long o = __shfl_down_sync(0xffffffffu, best, off);
                if (o > best) best = o;
            }
            if ((tid & 31) == 0) wred[tid >> 5] = best;
            __syncthreads();
            if (tid < 32) {
                best = wred[tid];
                for (int off = 16; off; off >>= 1) {
                    unsigned long long o = __shfl_down_sync(0xffffffffu, best, off);
                    if (o > best) best = o;
                }
                if (tid == 0) {
                    int gi = (int)(0xFFFFFFFFu - (unsigned int)(best & 0xFFFFFFFFull));
                    selected[k] = gi;
                    taken[gi >> 5] |= 1u << (gi & 31);
                }
            }
            __syncthreads();
        }
    }
    __syncthreads();

    // ---- Decode the 100 selected boxes: one warp per box ----
    const int lane = tid & 31;
    const int wid = tid >> 5;
    for (int k = wid; k < KN; k += 32) {
        int gi = selected[k];
        const float* img; int S, plane, loc, scale; float stridef;
        if (gi < 507)       { img = img13; S = 13; plane = 169;  loc = gi;        scale = 0; stridef = 32.f; }
        else if (gi < 2535) { img = img26; S = 26; plane = 676;  loc = gi - 507;  scale = 1; stridef = 16.f; }
        else                { img = img52; S = 52; plane = 2704; loc = gi - 2535; scale = 2; stridef = 8.f; }
        int a = loc % 3;
        int cell = loc / 3;
        int row = cell / S;
        int col = cell - row * S;
        size_t base = (size_t)(a * 85) * plane + row * S + col;

        float hv = 0.f;
        if (lane < 5) hv = img[base + (size_t)lane * plane];

        float bestv = -3.4e38f; int bestc = 1000;
        for (int cc = lane; cc < 80; cc += 32) {
            float v = img[base + (size_t)(5 + cc) * plane];
            if (v > bestv) { bestv = v; bestc = cc; }
        }
        for (int off = 16; off; off >>= 1) {
            float ov = __shfl_down_sync(0xffffffffu, bestv, off);
            int   oc = __shfl_down_sync(0xffffffffu, bestc, off);
            if (ov > bestv || (ov == bestv && oc < bestc)) { bestv = ov; bestc = oc; }
        }
        float p0 = __shfl_sync(0xffffffffu, hv, 0);
        float p1 = __shfl_sync(0xffffffffu, hv, 1);
        float p2 = __shfl_sync(0xffffffffu, hv, 2);
        float p3 = __shfl_sync(0xffffffffu, hv, 3);
        float p4 = __shfl_sync(0xffffffffu, hv, 4);
        if (lane == 0) {
            float conf = sigm(p0);
            float x = sigm(p1), y = sigm(p2);
            float ox = ((float)col + x) * stridef;
            float oy = ((float)row + y) * stridef;
            float w = expf(p3) * sAnc[(scale * 3 + a) * 2 + 0];
            float h = expf(p4) * sAnc[(scale * 3 + a) * 2 + 1];
            boxes[k][0] = ox - 0.5f * w;
            boxes[k][1] = oy - 0.5f * h;
            boxes[k][2] = ox + 0.5f * w;
            boxes[k][3] = oy + 0.5f * h;
            boxes[k][4] = (float)bestc;
            boxes[k][5] = conf;
        }
    }
    __syncthreads();

    // ---- NMS suppression masks: 100 rows x 128 bits ----
    for (int t = tid; t < KN * 4; t += NT) {
        int i = t >> 2, wIdx = t & 3;
        float ax1 = boxes[i][0], ay1 = boxes[i][1], ax2 = boxes[i][2], ay2 = boxes[i][3];
        float acls = boxes[i][4];
        float aarea = fmaxf(ax2 - ax1, 0.f) * fmaxf(ay2 - ay1, 0.f);
        unsigned int bits = 0;
        for (int jj = 0; jj < 32; jj++) {
            int j = wIdx * 32 + jj;
            if (j >= KN || j <= i) continue;
            if (boxes[j][4] != acls) continue;
            float x1 = fmaxf(ax1, boxes[j][0]);
            float y1 = fmaxf(ay1, boxes[j][1]);
            float x2 = fminf(ax2, boxes[j][2]);
            float y2 = fminf(ay2, boxes[j][3]);
            float inter = fmaxf(x2 - x1, 0.f) * fmaxf(y2 - y1, 0.f);
            float barea = fmaxf(boxes[j][2] - boxes[j][0], 0.f) *
                          fmaxf(boxes[j][3] - boxes[j][1], 0.f);
            float uni = aarea + barea - inter;
            float iou = inter / fmaxf(uni, 1e-9f);
            if (iou > IOU_T) bits |= 1u << jj;
        }
        nmask[i][wIdx] = bits;
    }
    __syncthreads();

    // ---- sequential greedy NMS (exact reference recurrence), bitwise ----
    if (tid == 0) {
        unsigned int kw0 = 0, kw1 = 0, kw2 = 0, kw3 = 0;
        for (int k = 0; k < KN; k++) {
            if (boxes[k][5] > thr) {
                if (k < 32)      kw0 |= 1u << k;
                else if (k < 64) kw1 |= 1u << (k - 32);
                else if (k < 96) kw2 |= 1u << (k - 64);
                else             kw3 |= 1u << (k - 96);
            }
        }
        unsigned int kw[4] = {kw0, kw1, kw2, kw3};
        for (int i = 0; i < KN; i++) {
            if ((kw[i >> 5] >> (i & 31)) & 1u) {
                kw[0] &= ~nmask[i][0];
                kw[1] &= ~nmask[i][1];
                kw[2] &= ~nmask[i][2];
                kw[3] &= ~nmask[i][3];
            }
        }
        keepW[0] = kw[0]; keepW[1] = kw[1]; keepW[2] = kw[2]; keepW[3] = kw[3];
    }
    __syncthreads();

    // ---- outputs: sel [B,100,6] then keep [B,100] as 0/1 floats ----
    const float* bx = &boxes[0][0];
    for (int t = tid; t < KN * 6; t += NT)
        out[(size_t)b * (KN * 6) + t] = bx[t];
    if (tid < KN)
        out[(size_t)B * (KN * 6) + (size_t)b * KN + tid] =
            ((keepW[tid >> 5] >> (tid & 31)) & 1u) ? 1.0f : 0.0f;
}

extern "C" void kernel_launch(void* const* d_in, const int* in_sizes, int n_in,
                              void* d_out, int out_size) {
    const float* o13 = (const float*)d_in[0];
    const float* o26 = (const float*)d_in[1];
    const float* o52 = (const float*)d_in[2];
    const float* anc = (const float*)d_in[3];
    const float* thr = (const float*)d_in[4];
    int B = in_sizes[0] / (255 * 13 * 13);
    float* out = (float*)d_out;
    yolo_nms_kernel<<<B, NT>>>(o13, o26, o52, anc, thr, out, B);
}

// round 4
// speedup vs baseline: 1.2302x; 1.2302x over previous
#include <cuda_runtime.h>
#include <math.h>

#define KN      100
#define NTOT    10647
#define NBINS   2048          // key = monotonic_map(bits) >> 21
#define NGRP    64
#define CAP     512
#define NT      1024
#define IOU_T   0.3f
#define TKWORDS ((NTOT + 31) / 32)

__device__ __forceinline__ float sigm(float x) { return 1.0f / (1.0f + expf(-x)); }

__device__ __forceinline__ unsigned int fmap(float x) {
    unsigned int b = __float_as_uint(x);
    return ((int)b < 0) ? ~b : (b | 0x80000000u);   // total-order map, monotonic in x
}

__device__ __forceinline__ unsigned long long make_key(float score, int gi) {
    return ((unsigned long long)__float_as_uint(score) << 32) |
           (unsigned long long)(0xFFFFFFFFu - (unsigned int)gi);   // lower idx wins ties
}

// raw objectness logit for global box index gi of one image
__device__ __forceinline__ float logit_of(int gi, const float* __restrict__ i13,
                                          const float* __restrict__ i26,
                                          const float* __restrict__ i52) {
    const float* img; int plane, loc;
    if (gi < 507)       { img = i13; plane = 169;  loc = gi; }
    else if (gi < 2535) { img = i26; plane = 676;  loc = gi - 507; }
    else                { img = i52; plane = 2704; loc = gi - 2535; }
    int a = loc % 3;
    int cell = loc / 3;
    return img[a * 85 * plane + cell];
}

__global__ __launch_bounds__(NT)
void yolo_nms_kernel(const float* __restrict__ o13, const float* __restrict__ o26,
                     const float* __restrict__ o52, const float* __restrict__ anc,
                     const float* __restrict__ thrp, float* __restrict__ out, int B)
{
    __shared__ unsigned short skey[NTOT + 1];     // 16-bit monotonic key per box
    __shared__ unsigned int hist[NBINS];
    __shared__ unsigned int gsum[NGRP];
    __shared__ int candIdx[CAP];
    __shared__ unsigned long long candKey[CAP];
    __shared__ unsigned long long wred[32];
    __shared__ int selected[KN];
    __shared__ float boxes[KN][6];
    __shared__ uint4 nmask4[KN];
    __shared__ unsigned int keepW[4];
    __shared__ float sAnc[18];
    __shared__ unsigned int taken[TKWORDS];
    __shared__ int sB, sCnt, sOvf;

    const int tid = threadIdx.x;
    const int b = blockIdx.x;
    const float thr = *thrp;
    const float lthr = logf(thr / (1.0f - thr));  // NaN/inf -> no fast positives -> fallback

    const float* img13 = o13 + (size_t)b * 255 * 169;
    const float* img26 = o26 + (size_t)b * 255 * 676;
    const float* img52 = o52 + (size_t)b * 255 * 2704;

    for (int i = tid; i < NBINS; i += NT) hist[i] = 0;
    if (tid < 18) sAnc[tid] = anc[tid];
    if (tid == 0) { sCnt = 0; sOvf = 0; sB = 0; }
    __syncthreads();

    // ---- Pass 1 (single global sweep, coalesced): cache 16-bit keys, histogram positives ----
    for (int t = tid; t < NTOT; t += NT) {
        const float* img; int plane, u, gioff;
        if (t < 507)       { img = img13; plane = 169;  u = t;        gioff = 0; }
        else if (t < 2535) { img = img26; plane = 676;  u = t - 507;  gioff = 507; }
        else               { img = img52; plane = 2704; u = t - 2535; gioff = 2535; }
        int a = u / plane;
        int cell = u - a * plane;                  // consecutive t -> consecutive cell
        float x = img[a * 85 * plane + cell];
        unsigned int m = fmap(x);
        int gi = gioff + cell * 3 + a;
        skey[gi] = (unsigned short)(m >> 16);
        if (x > lthr) atomicAdd(&hist[m >> 21], 1u);   // zeros never touch the histogram
    }
    __syncthreads();

    // ---- find threshold bin b*: parallel group sums + suffix sums ----
    if (tid < NGRP) {
        unsigned int s = 0;
        #pragma unroll 8
        for (int j = 0; j < 32; j++) s += hist[tid * 32 + j];
        gsum[tid] = s;
    }
    __syncthreads();
    if (tid < NGRP) {
        unsigned int suf = 0;
        for (int g = tid + 1; g < NGRP; g++) suf += gsum[g];
        unsigned int mine = gsum[tid];
        if (suf < KN && suf + mine >= KN) {        // exactly one thread (if total >= KN)
            unsigned int cum = suf;
            int bstar = tid * 32;
            for (int bb = tid * 32 + 31; bb >= tid * 32; bb--) {
                if (cum + hist[bb] >= KN) { bstar = bb; break; }
                cum += hist[bb];
            }
            sB = bstar;
        }
    }
    __syncthreads();
    const unsigned int bstar = (unsigned int)sB;
    // conf==1.0 saturation region: ordering by logit != ordering by (conf,idx) -> exact fallback
    const unsigned int satbin = (__float_as_uint(16.6f) | 0x80000000u) >> 21;
    if (tid == 0 && (bstar == 0 || bstar >= satbin)) sOvf = 1;
    __syncthreads();

    // ---- Pass 2: collect candidates from smem keys ----
    if (!sOvf) {
        for (int gi = tid; gi < NTOT; gi += NT) {
            if (((unsigned int)skey[gi] >> 5) >= bstar) {
                int pos = atomicAdd(&sCnt, 1);
                if (pos < CAP) candIdx[pos] = gi;
            }
        }
    }
    __syncthreads();
    if (tid == 0 && (sCnt > CAP || sCnt < KN)) sOvf = 1;
    __syncthreads();

    if (!sOvf) {
        const int T = sCnt;
        // exact keys for candidates (reload logit from global, L2-warm)
        if (tid < T) {
            int gi = candIdx[tid];
            float conf = sigm(logit_of(gi, img13, img26, img52));
            float score = (conf > thr) ? conf : 0.0f;
            candKey[tid] = make_key(score, gi);
        }
        __syncthreads();
        // rank selection: keys are unique -> ranks are a permutation
        if (tid < T) {
            unsigned long long mine = candKey[tid];
            int rank = 0;
            for (int j = 0; j < T; j++) rank += (candKey[j] > mine);
            if (rank < KN) selected[rank] = candIdx[tid];
        }
    } else {
        // ---- exact fallback: block-wide selection sort over all boxes ----
        for (int i = tid; i < TKWORDS; i += NT) taken[i] = 0;
        __syncthreads();
        for (int k = 0; k < KN; k++) {
            unsigned long long best = 0;
            for (int gi = tid; gi < NTOT; gi += NT) {
                if ((taken[gi >> 5] >> (gi & 31)) & 1u) continue;
                float conf = sigm(logit_of(gi, img13, img26, img52));
                float score = (conf > thr) ? conf : 0.0f;
                unsigned long long key = make_key(score, gi);
                if (key > best) best = key;
            }
            for (int off = 16; off; off >>= 1) {
                unsigned long long o = __shfl_down_sync(0xffffffffu, best, off);
                if (o > best) best = o;
            }
            if ((tid & 31) == 0) wred[tid >> 5] = best;
            __syncthreads();
            if (tid < 32) {
                best = wred[tid];
                for (int off = 16; off; off >>= 1) {
                    unsigned long long o = __shfl_down_sync(0xffffffffu, best, off);
                    if (o > best) best = o;
                }
                if (tid == 0) {
                    int gi = (int)(0xFFFFFFFFu - (unsigned int)(best & 0xFFFFFFFFull));
                    selected[k] = gi;
                    taken[gi >> 5] |= 1u << (gi & 31);
                }
            }
            __syncthreads();
        }
    }
    __syncthreads();

    // ---- Decode the 100 selected boxes: one warp per box ----
    const int lane = tid & 31;
    const int wid = tid >> 5;
    for (int k = wid; k < KN; k += 32) {
        int gi = selected[k];
        const float* img; int S, plane, loc, scale; float stridef;
        if (gi < 507)       { img = img13; S = 13; plane = 169;  loc = gi;        scale = 0; stridef = 32.f; }
        else if (gi < 2535) { img = img26; S = 26; plane = 676;  loc = gi - 507;  scale = 1; stridef = 16.f; }
        else                { img = img52; S = 52; plane = 2704; loc = gi - 2535; scale = 2; stridef = 8.f; }
        int a = loc % 3;
        int cell = loc / 3;
        int row = cell / S;
        int col = cell - row * S;
        size_t base = (size_t)(a * 85) * plane + cell;

        float hv = 0.f;
        if (lane < 5) hv = img[base + (size_t)lane * plane];

        float bestv = -3.4e38f; int bestc = 1000;
        #pragma unroll
        for (int r = 0; r < 3; r++) {
            int cc = lane + r * 32;
            if (cc < 80) {
                float v = img[base + (size_t)(5 + cc) * plane];
                if (v > bestv) { bestv = v; bestc = cc; }
            }
        }
        for (int off = 16; off; off >>= 1) {
            float ov = __shfl_down_sync(0xffffffffu, bestv, off);
            int   oc = __shfl_down_sync(0xffffffffu, bestc, off);
            if (ov > bestv || (ov == bestv && oc < bestc)) { bestv = ov; bestc = oc; }
        }
        float p0 = __shfl_sync(0xffffffffu, hv, 0);
        float p1 = __shfl_sync(0xffffffffu, hv, 1);
        float p2 = __shfl_sync(0xffffffffu, hv, 2);
        float p3 = __shfl_sync(0xffffffffu, hv, 3);
        float p4 = __shfl_sync(0xffffffffu, hv, 4);
        if (lane == 0) {
            float conf = sigm(p0);
            float x = sigm(p1), y = sigm(p2);
            float ox = ((float)col + x) * stridef;
            float oy = ((float)row + y) * stridef;
            float w = expf(p3) * sAnc[(scale * 3 + a) * 2 + 0];
            float h = expf(p4) * sAnc[(scale * 3 + a) * 2 + 1];
            boxes[k][0] = ox - 0.5f * w;
            boxes[k][1] = oy - 0.5f * h;
            boxes[k][2] = ox + 0.5f * w;
            boxes[k][3] = oy + 0.5f * h;
            boxes[k][4] = (float)bestc;
            boxes[k][5] = conf;
        }
    }
    __syncthreads();

    // ---- NMS suppression masks: 100 rows x 128 bits ----
    for (int t = tid; t < KN * 4; t += NT) {
        int i = t >> 2, wIdx = t & 3;
        float ax1 = boxes[i][0], ay1 = boxes[i][1], ax2 = boxes[i][2], ay2 = boxes[i][3];
        float acls = boxes[i][4];
        float aarea = fmaxf(ax2 - ax1, 0.f) * fmaxf(ay2 - ay1, 0.f);
        unsigned int bits = 0;
        for (int jj = 0; jj < 32; jj++) {
            int j = wIdx * 32 + jj;
            if (j >= KN || j <= i) continue;
            if (boxes[j][4] != acls) continue;
            float x1 = fmaxf(ax1, boxes[j][0]);
            float y1 = fmaxf(ay1, boxes[j][1]);
            float x2 = fminf(ax2, boxes[j][2]);
            float y2 = fminf(ay2, boxes[j][3]);
            float inter = fmaxf(x2 - x1, 0.f) * fmaxf(y2 - y1, 0.f);
            float barea = fmaxf(boxes[j][2] - boxes[j][0], 0.f) *
                          fmaxf(boxes[j][3] - boxes[j][1], 0.f);
            float uni = aarea + barea - inter;
            float iou = inter / fmaxf(uni, 1e-9f);
            if (iou > IOU_T) bits |= 1u << jj;
        }
        ((unsigned int*)&nmask4[i])[wIdx] = bits;
    }
    __syncthreads();

    // ---- sequential greedy NMS (exact reference recurrence), bitwise ----
    if (tid == 0) {
        unsigned int kw[4] = {0, 0, 0, 0};
        for (int k = 0; k < KN; k++)
            if (boxes[k][5] > thr) kw[k >> 5] |= 1u << (k & 31);
        #pragma unroll 4
        for (int i = 0; i < KN; i++) {
            uint4 m = nmask4[i];                   // LDS.128, pipelineable
            if ((kw[i >> 5] >> (i & 31)) & 1u) {
                kw[0] &= ~m.x; kw[1] &= ~m.y; kw[2] &= ~m.z; kw[3] &= ~m.w;
            }
        }
        keepW[0] = kw[0]; keepW[1] = kw[1]; keepW[2] = kw[2]; keepW[3] = kw[3];
    }
    __syncthreads();

    // ---- outputs: sel [B,100,6] then keep [B,100] as 0/1 floats ----
    const float* bx = &boxes[0][0];
    for (int t = tid; t < KN * 6; t += NT)
        out[(size_t)b * (KN * 6) + t] = bx[t];
    if (tid < KN)
        out[(size_t)B * (KN * 6) + (size_t)b * KN + tid] =
            ((keepW[tid >> 5] >> (tid & 31)) & 1u) ? 1.0f : 0.0f;
}

extern "C" void kernel_launch(void* const* d_in, const int* in_sizes, int n_in,
                              void* d_out, int out_size) {
    const float* o13 = (const float*)d_in[0];
    const float* o26 = (const float*)d_in[1];
    const float* o52 = (const float*)d_in[2];
    const float* anc = (const float*)d_in[3];
    const float* thr = (const float*)d_in[4];
    int B = in_sizes[0] / (255 * 13 * 13);
    float* out = (float*)d_out;
    yolo_nms_kernel<<<B, NT>>>(o13, o26, o52, anc, thr, out, B);
}

// round 8
// speedup vs baseline: 1.2643x; 1.0277x over previous
#include <cuda_runtime.h>
#include <math.h>

#define KN      100
#define NTOT    10647
#define NBINS   2048          // key = monotonic_map(bits) >> 21
#define NGRP    64
#define CAP     512
#define NT      1024
#define IOU_T   0.3f
#define TKWORDS ((NTOT + 31) / 32)
#define MAXB    64

__device__ int   g_selected[MAXB * KN];
__device__ float g_boxes[MAXB * KN * 6];

__device__ __forceinline__ float sigm(float x) { return 1.0f / (1.0f + expf(-x)); }

__device__ __forceinline__ unsigned int fmap(float x) {
    unsigned int b = __float_as_uint(x);
    return ((int)b < 0) ? ~b : (b | 0x80000000u);   // total-order map, monotonic in x
}

__device__ __forceinline__ unsigned long long make_key(float score, int gi) {
    return ((unsigned long long)__float_as_uint(score) << 32) |
           (unsigned long long)(0xFFFFFFFFu - (unsigned int)gi);   // lower idx wins ties
}

// raw objectness logit for global box index gi of one image
__device__ __forceinline__ float logit_of(int gi, const float* __restrict__ i13,
                                          const float* __restrict__ i26,
                                          const float* __restrict__ i52) {
    const float* img; int plane, loc;
    if (gi < 507)       { img = i13; plane = 169;  loc = gi; }
    else if (gi < 2535) { img = i26; plane = 676;  loc = gi - 507; }
    else                { img = i52; plane = 2704; loc = gi - 2535; }
    int a = loc % 3;
    int cell = loc / 3;
    return img[a * 85 * plane + cell];
}

// ========================= Kernel 1: top-100 selection =========================
__global__ __launch_bounds__(NT)
void k_select(const float* __restrict__ o13, const float* __restrict__ o26,
              const float* __restrict__ o52, const float* __restrict__ thrp)
{
    __shared__ unsigned short skey[NTOT + 1];
    __shared__ unsigned int hist[NBINS];
    __shared__ unsigned int gsum[NGRP];
    __shared__ int candIdx[CAP];
    __shared__ unsigned long long candKey[CAP];
    __shared__ unsigned long long wred[32];
    __shared__ int selected[KN];
    __shared__ unsigned int taken[TKWORDS];
    __shared__ int sB, sCnt, sOvf;

    const int tid = threadIdx.x;
    const int b = blockIdx.x;
    const float thr = *thrp;
    const float lthr = logf(thr / (1.0f - thr));  // NaN/inf -> no fast positives -> fallback

    const float* img13 = o13 + (size_t)b * 255 * 169;
    const float* img26 = o26 + (size_t)b * 255 * 676;
    const float* img52 = o52 + (size_t)b * 255 * 2704;

    for (int i = tid; i < NBINS; i += NT) hist[i] = 0;
    if (tid == 0) { sCnt = 0; sOvf = 0; sB = 0; }
    __syncthreads();

    // ---- Pass 1 (single coalesced sweep): cache 16-bit keys, histogram positives ----
    for (int t = tid; t < NTOT; t += NT) {
        const float* img; int plane, u, gioff;
        if (t < 507)       { img = img13; plane = 169;  u = t;        gioff = 0; }
        else if (t < 2535) { img = img26; plane = 676;  u = t - 507;  gioff = 507; }
        else               { img = img52; plane = 2704; u = t - 2535; gioff = 2535; }
        int a = u / plane;
        int cell = u - a * plane;
        float x = img[a * 85 * plane + cell];
        unsigned int m = fmap(x);
        int gi = gioff + cell * 3 + a;
        skey[gi] = (unsigned short)(m >> 16);
        if (x > lthr) atomicAdd(&hist[m >> 21], 1u);
    }
    __syncthreads();

    // ---- find threshold bin b* ----
    if (tid < NGRP) {
        unsigned int s = 0;
        #pragma unroll 8
        for (int j = 0; j < 32; j++) s += hist[tid * 32 + j];
        gsum[tid] = s;
    }
    __syncthreads();
    if (tid < NGRP) {
        unsigned int suf = 0;
        for (int g = tid + 1; g < NGRP; g++) suf += gsum[g];
        unsigned int mine = gsum[tid];
        if (suf < KN && suf + mine >= KN) {
            unsigned int cum = suf;
            int bstar = tid * 32;
            for (int bb = tid * 32 + 31; bb >= tid * 32; bb--) {
                if (cum + hist[bb] >= KN) { bstar = bb; break; }
                cum += hist[bb];
            }
            sB = bstar;
        }
    }
    __syncthreads();
    const unsigned int bstar = (unsigned int)sB;
    const unsigned int satbin = (__float_as_uint(16.6f) | 0x80000000u) >> 21;
    if (tid == 0 && (bstar == 0 || bstar >= satbin)) sOvf = 1;
    __syncthreads();

    // ---- Pass 2: collect candidates from smem keys ----
    if (!sOvf) {
        for (int gi = tid; gi < NTOT; gi += NT) {
            if (((unsigned int)skey[gi] >> 5) >= bstar) {
                int pos = atomicAdd(&sCnt, 1);
                if (pos < CAP) candIdx[pos] = gi;
            }
        }
    }
    __syncthreads();
    if (tid == 0 && (sCnt > CAP || sCnt < KN)) sOvf = 1;
    __syncthreads();

    if (!sOvf) {
        const int T = sCnt;
        if (tid < T) {
            int gi = candIdx[tid];
            float conf = sigm(logit_of(gi, img13, img26, img52));
            float score = (conf > thr) ? conf : 0.0f;
            candKey[tid] = make_key(score, gi);
        }
        __syncthreads();
        if (tid < T) {
            unsigned long long mine = candKey[tid];
            int rank = 0;
            for (int j = 0; j < T; j++) rank += (candKey[j] > mine);
            if (rank < KN) selected[rank] = candIdx[tid];
        }
    } else {
        // ---- exact fallback: block-wide selection sort ----
        for (int i = tid; i < TKWORDS; i += NT) taken[i] = 0;
        __syncthreads();
        for (int k = 0; k < KN; k++) {
            unsigned long long best = 0;
            for (int gi = tid; gi < NTOT; gi += NT) {
                if ((taken[gi >> 5] >> (gi & 31)) & 1u) continue;
                float conf = sigm(logit_of(gi, img13, img26, img52));
                float score = (conf > thr) ? conf : 0.0f;
                unsigned long long key = make_key(score, gi);
                if (key > best) best = key;
            }
            for (int off = 16; off; off >>= 1) {
                unsigned long long o = __shfl_down_sync(0xffffffffu, best, off);
                if (o > best) best = o;
            }
            if ((tid & 31) == 0) wred[tid >> 5] = best;
            __syncthreads();
            if (tid < 32) {
                best = wred[tid];
                for (int off = 16; off; off >>= 1) {
                    unsigned long long o = __shfl_down_sync(0xffffffffu, best, off);
                    if (o > best) best = o;
                }
                if (tid == 0) {
                    int gi = (int)(0xFFFFFFFFu - (unsigned int)(best & 0xFFFFFFFFull));
                    selected[k] = gi;
                    taken[gi >> 5] |= 1u << (gi & 31);
                }
            }
            __syncthreads();
        }
    }
    __syncthreads();
    if (tid < KN) g_selected[b * KN + tid] = selected[tid];
}

// ========================= Kernel 2: decode (one warp per box, chip-wide) =========================
__global__ __launch_bounds__(256)
void k_decode(const float* __restrict__ o13, const float* __restrict__ o26,
              const float* __restrict__ o52, const float* __restrict__ anc)
{
    const int b = blockIdx.y;
    const int w = threadIdx.x >> 5;
    const int lane = threadIdx.x & 31;
    const int k = blockIdx.x * 8 + w;
    if (k >= KN) return;

    const float* img13 = o13 + (size_t)b * 255 * 169;
    const float* img26 = o26 + (size_t)b * 255 * 676;
    const float* img52 = o52 + (size_t)b * 255 * 2704;

    int gi = g_selected[b * KN + k];
    const float* img; int S, plane, loc, scale; float stridef;
    if (gi < 507)       { img = img13; S = 13; plane = 169;  loc = gi;        scale = 0; stridef = 32.f; }
    else if (gi < 2535) { img = img26; S = 26; plane = 676;  loc = gi - 507;  scale = 1; stridef = 16.f; }
    else                { img = img52; S = 52; plane = 2704; loc = gi - 2535; scale = 2; stridef = 8.f; }
    int a = loc % 3;
    int cell = loc / 3;
    int row = cell / S;
    int col = cell - row * S;
    size_t base = (size_t)(a * 85) * plane + cell;

    float hv = 0.f;
    if (lane < 5) hv = img[base + (size_t)lane * plane];

    float bestv = -3.4e38f; int bestc = 1000;
    #pragma unroll
    for (int r = 0; r < 3; r++) {
        int cc = lane + r * 32;
        if (cc < 80) {
            float v = img[base + (size_t)(5 + cc) * plane];
            if (v > bestv) { bestv = v; bestc = cc; }
        }
    }
    for (int off = 16; off; off >>= 1) {
        float ov = __shfl_down_sync(0xffffffffu, bestv, off);
        int   oc = __shfl_down_sync(0xffffffffu, bestc, off);
        if (ov > bestv || (ov == bestv && oc < bestc)) { bestv = ov; bestc = oc; }
    }
    float p0 = __shfl_sync(0xffffffffu, hv, 0);
    float p1 = __shfl_sync(0xffffffffu, hv, 1);
    float p2 = __shfl_sync(0xffffffffu, hv, 2);
    float p3 = __shfl_sync(0xffffffffu, hv, 3);
    float p4 = __shfl_sync(0xffffffffu, hv, 4);
    if (lane == 0) {
        float conf = sigm(p0);
        float x = sigm(p1), y = sigm(p2);
        float ox = ((float)col + x) * stridef;
        float oy = ((float)row + y) * stridef;
        float w_ = expf(p3) * anc[(scale * 3 + a) * 2 + 0];
        float h_ = expf(p4) * anc[(scale * 3 + a) * 2 + 1];
        float* bo = &g_boxes[(b * KN + k) * 6];
        bo[0] = ox - 0.5f * w_;
        bo[1] = oy - 0.5f * h_;
        bo[2] = ox + 0.5f * w_;
        bo[3] = oy + 0.5f * h_;
        bo[4] = (float)bestc;
        bo[5] = conf;
    }
}

// ========================= Kernel 3: NMS + outputs =========================
__global__ __launch_bounds__(512)
void k_nms(const float* __restrict__ thrp, float* __restrict__ out, int B)
{
    __shared__ float boxes[KN][6];
    __shared__ uint4 nmask4[KN];
    __shared__ unsigned int keepW[4];

    const int tid = threadIdx.x;
    const int b = blockIdx.x;
    const float thr = *thrp;

    for (int t = tid; t < KN * 6; t += 512)
        (&boxes[0][0])[t] = g_boxes[b * KN * 6 + t];
    __syncthreads();

    // masks: 100 rows x 128 bits
    if (tid < KN * 4) {
        int i = tid >> 2, wIdx = tid & 3;
        float ax1 = boxes[i][0], ay1 = boxes[i][1], ax2 = boxes[i][2], ay2 = boxes[i][3];
        float acls = boxes[i][4];
        float aarea = fmaxf(ax2 - ax1, 0.f) * fmaxf(ay2 - ay1, 0.f);
        unsigned int bits = 0;
        for (int jj = 0; jj < 32; jj++) {
            int j = wIdx * 32 + jj;
            if (j >= KN || j <= i) continue;
            if (boxes[j][4] != acls) continue;
            float x1 = fmaxf(ax1, boxes[j][0]);
            float y1 = fmaxf(ay1, boxes[j][1]);
            float x2 = fminf(ax2, boxes[j][2]);
            float y2 = fminf(ay2, boxes[j][3]);
            float inter = fmaxf(x2 - x1, 0.f) * fmaxf(y2 - y1, 0.f);
            float barea = fmaxf(boxes[j][2] - boxes[j][0], 0.f) *
                          fmaxf(boxes[j][3] - boxes[j][1], 0.f);
            float uni = aarea + barea - inter;
            float iou = inter / fmaxf(uni, 1e-9f);
            if (iou > IOU_T) bits |= 1u << jj;
        }
        ((unsigned int*)&nmask4[i])[wIdx] = bits;
    }
    __syncthreads();

    // exact sequential greedy recurrence, bitwise
    if (tid == 0) {
        unsigned int kw[4] = {0, 0, 0, 0};
        for (int k = 0; k < KN; k++)
            if (boxes[k][5] > thr) kw[k >> 5] |= 1u << (k & 31);
        #pragma unroll 4
        for (int i = 0; i < KN; i++) {
            uint4 m = nmask4[i];
            if ((kw[i >> 5] >> (i & 31)) & 1u) {
                kw[0] &= ~m.x; kw[1] &= ~m.y; kw[2] &= ~m.z; kw[3] &= ~m.w;
            }
        }
        keepW[0] = kw[0]; keepW[1] = kw[1]; keepW[2] = kw[2]; keepW[3] = kw[3];
    }
    __syncthreads();

    const float* bx = &boxes[0][0];
    for (int t = tid; t < KN * 6; t += 512)
        out[(size_t)b * (KN * 6) + t] = bx[t];
    if (tid < KN)
        out[(size_t)B * (KN * 6) + (size_t)b * KN + tid] =
            ((keepW[tid >> 5] >> (tid & 31)) & 1u) ? 1.0f : 0.0f;
}

extern "C" void kernel_launch(void* const* d_in, const int* in_sizes, int n_in,
                              void* d_out, int out_size) {
    const float* o13 = (const float*)d_in[0];
    const float* o26 = (const float*)d_in[1];
    const float* o52 = (const float*)d_in[2];
    const float* anc = (const float*)d_in[3];
    const float* thr = (const float*)d_in[4];
    int B = in_sizes[0] / (255 * 13 * 13);
    float* out = (float*)d_out;

    k_select<<<B, NT>>>(o13, o26, o52, thr);
    dim3 gdec((KN + 7) / 8, B);
    k_decode<<<gdec, 256>>>(o13, o26, o52, anc);
    k_nms<<<B, 512>>>(thr, out, B);
}